// round 15
// baseline (speedup 1.0000x reference)
#include <cuda_runtime.h>
#include <cuda_fp16.h>

typedef unsigned int u32;

#define SEQ   256
#define LAB   128
#define BATCH 8192
#define ROWS  16
#define NBLK  (BATCH / ROWS)   // 512
#define NTHR  128              // 4 warps
#define KP    88               // A k-stride (fp16); 176B rows, conflict-free ldm4
#define RB    176
#define KPB   80               // B k-stride; 160B rows (2-way ldm2 conflict, acceptable)
#define RBB   160
#define KC    5                // K=80: 64 h + 8 x + 1 bias + pad

// ---- SMEM byte offsets (per CTA ~50.3KB -> 4 CTAs/SM) ----
#define SA    0                 // A: [2 buf][hi|lo][16][88]
#define ABUF  5632
#define ALO   2816
#define SBM   11264             // B main [192][80]: rows j<128 -> n=j (r,z); j>=128 -> n=j+64 (nh)
#define SNIH  (SBM + 192*RBB)   // 41984: ni-hi compact [64][24]
#define SNIL  (SNIH + 64*48)    // 45056: ni-lo compact [64][24]
#define SWOUT (SNIL + 64*48)    // 48128: [64][8] f32
#define SBOUT (SWOUT + 2048)    // 50176
#define STOT  (SBOUT + 128)     // 50304

static __device__ __forceinline__ u32 sptr(const void* p) {
    return (u32)__cvta_generic_to_shared(p);
}
static __device__ __forceinline__ void ldm4(u32* r, u32 a) {
    asm volatile("ldmatrix.sync.aligned.m8n8.x4.shared.b16 {%0,%1,%2,%3},[%4];"
        : "=r"(r[0]), "=r"(r[1]), "=r"(r[2]), "=r"(r[3]) : "r"(a));
}
static __device__ __forceinline__ void ldm2(u32* r, u32 a) {
    asm volatile("ldmatrix.sync.aligned.m8n8.x2.shared.b16 {%0,%1},[%2];"
        : "=r"(r[0]), "=r"(r[1]) : "r"(a));
}
static __device__ __forceinline__ void mmaop(float* d, const u32* a, const u32* b) {
    asm volatile("mma.sync.aligned.m16n8k16.row.col.f32.f16.f16.f32 "
        "{%0,%1,%2,%3},{%4,%5,%6,%7},{%8,%9},{%0,%1,%2,%3};"
        : "+f"(d[0]), "+f"(d[1]), "+f"(d[2]), "+f"(d[3])
        : "r"(a[0]), "r"(a[1]), "r"(a[2]), "r"(a[3]), "r"(b[0]), "r"(b[1]));
}
static __device__ __forceinline__ float tanha(float x) {
    float y; asm("tanh.approx.f32 %0,%1;" : "=f"(y) : "f"(x)); return y;
}
static __device__ __forceinline__ float sigt(float x) { return fmaf(0.5f, tanha(0.5f * x), 0.5f); }

// value of B[n][k]
static __device__ __forceinline__ float bval(int n, int k,
                                             const float* Wih, const float* Whh,
                                             const float* bih, const float* bhh) {
    if (k < 64) {
        if (n < 128)  return Whh[n * 64 + k];            // r,z
        if (n >= 192) return Whh[(n - 64) * 64 + k];     // nh
        return 0.0f;                                     // ni: no recurrent
    }
    if (k < 72) return (n < 192) ? Wih[n * 8 + (k - 64)] : 0.0f;
    if (k == 72) return (n < 128) ? bih[n] + bhh[n] : (n < 192 ? bih[n] : bhh[n - 64]);
    return 0.0f;
}

// build main region [192][80] for one term (0=hi, 1=lo)
static __device__ void build_main(half* Bm,
                                  const float* __restrict__ Wih, const float* __restrict__ Whh,
                                  const float* __restrict__ bih, const float* __restrict__ bhh,
                                  int term, int tid) {
    for (int i = tid; i < 192 * KPB; i += NTHR) {
        int j = i / KPB, k = i % KPB;
        int n = (j < 128) ? j : j + 64;
        float v = bval(n, k, Wih, Whh, bih, bhh);
        half h = __float2half_rn(v);
        if (term) h = __float2half_rn(v - __half2float(h));
        Bm[i] = h;
    }
}
// build ni compact [64][24] (k = 64 + c; c>=16 pad)
static __device__ void build_ni(half* Bc,
                                const float* __restrict__ Wih, const float* __restrict__ bih,
                                int term, int tid) {
    for (int i = tid; i < 64 * 24; i += NTHR) {
        int r = i / 24, c = i % 24;
        int n = 128 + r;
        float v = 0.0f;
        if (c < 8) v = Wih[n * 8 + c];
        else if (c == 8) v = bih[n];
        half h = __float2half_rn(v);
        if (term) h = __float2half_rn(v - __half2float(h));
        Bc[i] = h;
    }
}

// Gates in regs; write h' (hi/lo) into next A buffer. Warp w owns unit pairs
// {w*8.., w*8+32..} (tile pair tp=0/1 per gate).
static __device__ __forceinline__ void epi(half* AhiN, half* AloN, int warp, int lane,
                                           float (&D)[8][4], float (&hold)[2][4]) {
    const int lr = lane >> 2;
    const int cl = 2 * (lane & 3);
    #pragma unroll
    for (int tp = 0; tp < 2; tp++) {
        float h[4];
        #pragma unroll
        for (int j = 0; j < 4; j++) {
            float R = sigt(D[0 + tp][j]);
            float Z = sigt(D[2 + tp][j]);
            float N = tanha(fmaf(R, D[6 + tp][j], D[4 + tp][j]));
            h[j] = fmaf(Z, hold[tp][j] - N, N);
            hold[tp][j] = h[j];
        }
        int cu = warp * 8 + tp * 32 + cl;
        half2 h2a = __floats2half2_rn(h[0], h[1]);
        half2 l2a = __floats2half2_rn(h[0] - __low2float(h2a), h[1] - __high2float(h2a));
        half2 h2b = __floats2half2_rn(h[2], h[3]);
        half2 l2b = __floats2half2_rn(h[2] - __low2float(h2b), h[3] - __high2float(h2b));
        *(half2*)(AhiN + lr * KP + cu)       = h2a;
        *(half2*)(AloN + lr * KP + cu)       = l2a;
        *(half2*)(AhiN + (lr + 8) * KP + cu) = h2b;
        *(half2*)(AloN + (lr + 8) * KP + cu) = l2b;
    }
}

static __device__ __forceinline__ void stage_x(half* Ahi, half* Alo, int row, const float* v) {
    #pragma unroll
    for (int j = 0; j < 4; j++) {
        float a = v[2 * j], b = v[2 * j + 1];
        half2 h2 = __floats2half2_rn(a, b);
        half2 l2 = __floats2half2_rn(a - __low2float(h2), b - __high2float(h2));
        *(half2*)(Ahi + row * KP + 64 + 2 * j) = h2;
        *(half2*)(Alo + row * KP + 64 + 2 * j) = l2;
    }
}

static __device__ __forceinline__ float oproj(const half* Ahi, const half* Alo,
                                              const float* wo, float acc, int r, int oo) {
    const half2* rh = (const half2*)(Ahi + r * KP);
    const half2* rl = (const half2*)(Alo + r * KP);
    #pragma unroll 8
    for (int k2 = 0; k2 < 32; k2++) {
        float2 hq = __half22float2(rh[k2]);
        float2 lq = __half22float2(rl[k2]);
        acc = fmaf(hq.x + lq.x, wo[(2 * k2) * 8 + oo],
              fmaf(hq.y + lq.y, wo[(2 * k2 + 1) * 8 + oo], acc));
    }
    return acc;
}

__global__ __launch_bounds__(NTHR, 4)
void seq2seq_mma_kernel(const float* __restrict__ x,
                        const float* __restrict__ xy,
                        const float* __restrict__ eWih, const float* __restrict__ eWhh,
                        const float* __restrict__ ebih, const float* __restrict__ ebhh,
                        const float* __restrict__ dWih, const float* __restrict__ dWhh,
                        const float* __restrict__ dbih, const float* __restrict__ dbhh,
                        const float* __restrict__ Wout, const float* __restrict__ bout,
                        float* __restrict__ out)
{
    extern __shared__ char smem[];
    half*  Bm  = (half*)(smem + SBM);
    half*  Bnh = (half*)(smem + SNIH);
    half*  Bnl = (half*)(smem + SNIL);
    float* wo  = (float*)(smem + SWOUT);
    float* bo  = (float*)(smem + SBOUT);

    const int tid  = threadIdx.x;
    const int lane = tid & 31;
    const int warp = tid >> 5;          // 0..3
    const int rowb = blockIdx.x * ROWS;

    // ---- zero A, load wout/bout ----
    for (int i = tid * 16; i < SBM; i += NTHR * 16) *(uint4*)(smem + i) = make_uint4(0, 0, 0, 0);
    for (int i = tid; i < 512; i += NTHR) { int k = i >> 3, o = i & 7; wo[i] = Wout[o * 64 + k]; }
    if (tid < 8) bo[tid] = bout[tid];
    __syncthreads();
    if (tid < ROWS) {
        ((half*)(smem + SA))[tid * KP + 72]        = __float2half(1.0f);
        ((half*)(smem + SA + ABUF))[tid * KP + 72] = __float2half(1.0f);
        const float4* p = (const float4*)(x + ((size_t)rowb + tid) * 8);
        float4 a = p[0], b = p[1];
        float v[8] = {a.x, a.y, a.z, a.w, b.x, b.y, b.z, b.w};
        stage_x((half*)(smem + SA), (half*)(smem + SA + ALO), tid, v);
    }
    __syncthreads();

    // ---- fragment base addresses ----
    const u32 fbB  = sptr(Bm)  + (u32)((lane & 7) * RBB + ((lane >> 3) & 1) * 16);
    const u32 fbNh = sptr(Bnh) + (u32)((lane & 7) * 48 + ((lane >> 3) & 1) * 16);
    const u32 fbNl = sptr(Bnl) + (u32)((lane & 7) * 48 + ((lane >> 3) & 1) * 16);
    // tile row bases in main region (j index): r: w*8,(w+4)*8 ; z: (8+w)*8,(12+w)*8 ; nh: 128+w*8,160+w*8
    u32 aR[2], aZ[2], aN[2], aNiH[2], aNiL[2];
    aR[0] = fbB + (u32)((warp)      * 8 * RBB);  aR[1] = fbB + (u32)((warp + 4)  * 8 * RBB);
    aZ[0] = fbB + (u32)((8 + warp)  * 8 * RBB);  aZ[1] = fbB + (u32)((12 + warp) * 8 * RBB);
    aN[0] = fbB + (u32)((128 + warp * 8) * RBB); aN[1] = fbB + (u32)((160 + warp * 8) * RBB);
    aNiH[0] = fbNh + (u32)(warp * 8 * 48);  aNiH[1] = fbNh + (u32)((32 + warp * 8) * 48);
    aNiL[0] = fbNl + (u32)(warp * 8 * 48);  aNiL[1] = fbNl + (u32)((32 + warp * 8) * 48);

    u32 BhR[2][KC][2], BhZ[2][KC][2], BhN[2][KC][2];   // resident hi frags (60 regs)

    // ---- encoder B: hi -> regs, then lo resident in SMEM ----
    build_main(Bm, eWih, eWhh, ebih, ebhh, 0, tid);
    __syncthreads();
    #pragma unroll
    for (int tp = 0; tp < 2; tp++)
        #pragma unroll
        for (int kc = 0; kc < KC; kc++) {
            ldm2(BhR[tp][kc], aR[tp] + kc * 32);
            ldm2(BhZ[tp][kc], aZ[tp] + kc * 32);
            ldm2(BhN[tp][kc], aN[tp] + kc * 32);
        }
    __syncthreads();
    build_main(Bm, eWih, eWhh, ebih, ebhh, 1, tid);
    build_ni(Bnh, eWih, ebih, 0, tid);
    build_ni(Bnl, eWih, ebih, 1, tid);
    __syncthreads();

    u32 aoff;
    { int t8 = lane >> 3, lr = lane & 7;
      aoff = (u32)(((t8 & 1) * 8 + lr) * RB + (t8 >> 1) * 16); }
    const u32 sbA = sptr(smem + SA);

    float D[8][4];
    float hold[2][4];
    #pragma unroll
    for (int tp = 0; tp < 2; tp++)
        #pragma unroll
        for (int j = 0; j < 4; j++) hold[tp][j] = 0.0f;

    int b = 0;

    // one full GEMM step: fills D[8][4]
    #define GEMM_STEP(ABASE)                                                        \
    do {                                                                            \
        _Pragma("unroll")                                                           \
        for (int q = 0; q < 8; q++)                                                 \
            _Pragma("unroll")                                                       \
            for (int e = 0; e < 4; e++) D[q][e] = 0.0f;                             \
        _Pragma("unroll")                                                           \
        for (int kc = 0; kc < KC; kc++) {                                           \
            u32 ah[4], al[4];                                                       \
            ldm4(ah, (ABASE) + kc * 32);                                            \
            ldm4(al, (ABASE) + ALO + kc * 32);                                      \
            _Pragma("unroll")                                                       \
            for (int tp = 0; tp < 2; tp++) {                                        \
                u32 lr_[2], lz_[2], ln_[2];                                         \
                ldm2(lr_, aR[tp] + kc * 32);                                        \
                ldm2(lz_, aZ[tp] + kc * 32);                                        \
                ldm2(ln_, aN[tp] + kc * 32);                                        \
                mmaop(D[0 + tp], ah, BhR[tp][kc]); mmaop(D[0 + tp], al, BhR[tp][kc]); \
                mmaop(D[0 + tp], ah, lr_);                                          \
                mmaop(D[2 + tp], ah, BhZ[tp][kc]); mmaop(D[2 + tp], al, BhZ[tp][kc]); \
                mmaop(D[2 + tp], ah, lz_);                                          \
                mmaop(D[6 + tp], ah, BhN[tp][kc]); mmaop(D[6 + tp], al, BhN[tp][kc]); \
                mmaop(D[6 + tp], ah, ln_);                                          \
            }                                                                       \
            if (kc == KC - 1) {                                                     \
                _Pragma("unroll")                                                   \
                for (int tp = 0; tp < 2; tp++) {                                    \
                    u32 nh_[2], nl_[2];                                             \
                    ldm2(nh_, aNiH[tp]);                                            \
                    ldm2(nl_, aNiL[tp]);                                            \
                    mmaop(D[4 + tp], ah, nh_); mmaop(D[4 + tp], al, nh_);           \
                    mmaop(D[4 + tp], ah, nl_);                                      \
                }                                                                   \
            }                                                                       \
        }                                                                           \
    } while (0)

    // =========================== ENCODER (1 sync/step) ===========================
    for (int t = 0; t < SEQ; t++) {
        float xv[8];
        const bool pf = (tid < ROWS) && (t + 1 < SEQ);
        if (pf) {
            const float4* p = (const float4*)(x + ((size_t)(t + 1) * BATCH + rowb + tid) * 8);
            float4 a = p[0], c = p[1];
            xv[0]=a.x; xv[1]=a.y; xv[2]=a.z; xv[3]=a.w; xv[4]=c.x; xv[5]=c.y; xv[6]=c.z; xv[7]=c.w;
        }
        GEMM_STEP(sbA + (u32)(b * ABUF) + aoff);
        int nb = b ^ 1;
        half* AhiN = (half*)(smem + SA + nb * ABUF);
        half* AloN = AhiN + ALO / 2;
        epi(AhiN, AloN, warp, lane, D, hold);
        if (pf) stage_x(AhiN, AloN, tid, xv);
        __syncthreads();
        b = nb;
    }

    // ---- decoder B + xy[0] ----
    build_main(Bm, dWih, dWhh, dbih, dbhh, 0, tid);
    __syncthreads();
    #pragma unroll
    for (int tp = 0; tp < 2; tp++)
        #pragma unroll
        for (int kc = 0; kc < KC; kc++) {
            ldm2(BhR[tp][kc], aR[tp] + kc * 32);
            ldm2(BhZ[tp][kc], aZ[tp] + kc * 32);
            ldm2(BhN[tp][kc], aN[tp] + kc * 32);
        }
    __syncthreads();
    build_main(Bm, dWih, dWhh, dbih, dbhh, 1, tid);
    build_ni(Bnh, dWih, dbih, 0, tid);
    build_ni(Bnl, dWih, dbih, 1, tid);
    if (tid < ROWS) {
        const float4* p = (const float4*)(xy + ((size_t)rowb + tid) * 8);
        float4 a = p[0], c = p[1];
        float v[8] = {a.x, a.y, a.z, a.w, c.x, c.y, c.z, c.w};
        half* Ahi = (half*)(smem + SA + b * ABUF);
        stage_x(Ahi, Ahi + ALO / 2, tid, v);
    }
    __syncthreads();

    const int orr = tid >> 3, oo = tid & 7;    // 16 rows x 8 outs = 128 threads
    const float bop = bo[oo];

    // =========================== DECODER ===========================
    for (int t = 0; t < LAB; t++) {
        GEMM_STEP(sbA + (u32)(b * ABUF) + aoff);
        int nb = b ^ 1;
        half* AhiN = (half*)(smem + SA + nb * ABUF);
        half* AloN = AhiN + ALO / 2;
        epi(AhiN, AloN, warp, lane, D, hold);
        __syncthreads();                       // h_{t+1} visible

        {
            float acc = oproj(AhiN, AloN, wo, bop, orr, oo);
            out[((size_t)t * BATCH + rowb + orr) * 8 + oo] = acc;
            if (t + 1 < LAB) {                 // feedback x
                half hh = __float2half_rn(acc);
                AhiN[orr * KP + 64 + oo] = hh;
                AloN[orr * KP + 64 + oo] = __float2half_rn(acc - __half2float(hh));
            }
        }
        __syncthreads();
        b = nb;
    }
}

extern "C" void kernel_launch(void* const* d_in, const int* in_sizes, int n_in,
                              void* d_out, int out_size) {
    (void)in_sizes; (void)n_in; (void)out_size;
    cudaFuncSetAttribute(seq2seq_mma_kernel,
                         cudaFuncAttributeMaxDynamicSharedMemorySize, STOT);
    seq2seq_mma_kernel<<<NBLK, NTHR, STOT>>>(
        (const float*)d_in[0], (const float*)d_in[1],
        (const float*)d_in[2], (const float*)d_in[3],
        (const float*)d_in[4], (const float*)d_in[5],
        (const float*)d_in[6], (const float*)d_in[7],
        (const float*)d_in[8], (const float*)d_in[9],
        (const float*)d_in[10], (const float*)d_in[11],
        (float*)d_out);
}

// round 16
// speedup vs baseline: 1.4241x; 1.4241x over previous
#include <cuda_runtime.h>
#include <cuda_fp16.h>

typedef unsigned int u32;

#define SEQ   256
#define LAB   128
#define BATCH 8192
#define ROWS  32
#define NBLK  (BATCH / ROWS)   // 256
#define NTHR  256
#define KP    88
#define RB    176
#define KC    5                // K=80: 64 h + 8 x + 1 bias + pad

// ---- SMEM byte offsets ----
// A: [2 buf][hi|lo][32][88] fp16.  buf stride 11264, hi->lo +5632
#define SA    0
#define ABUF  11264
#define ALO   5632
#define SB    22528            // B scratch (build + frag load only)
#define SWOUT 67584            // [64][8] f32
#define SBOUT 69632            // [8] f32
#define STOT  69696

static __device__ __forceinline__ u32 sptr(const void* p) {
    return (u32)__cvta_generic_to_shared(p);
}
static __device__ __forceinline__ void ldm4(u32* r, u32 a) {
    asm volatile("ldmatrix.sync.aligned.m8n8.x4.shared.b16 {%0,%1,%2,%3},[%4];"
        : "=r"(r[0]), "=r"(r[1]), "=r"(r[2]), "=r"(r[3]) : "r"(a));
}
static __device__ __forceinline__ void ldm2(u32* r, u32 a) {
    asm volatile("ldmatrix.sync.aligned.m8n8.x2.shared.b16 {%0,%1},[%2];"
        : "=r"(r[0]), "=r"(r[1]) : "r"(a));
}
static __device__ __forceinline__ void mmaop(float* d, const u32* a, const u32* b) {
    asm volatile("mma.sync.aligned.m16n8k16.row.col.f32.f16.f16.f32 "
        "{%0,%1,%2,%3},{%4,%5,%6,%7},{%8,%9},{%0,%1,%2,%3};"
        : "+f"(d[0]), "+f"(d[1]), "+f"(d[2]), "+f"(d[3])
        : "r"(a[0]), "r"(a[1]), "r"(a[2]), "r"(a[3]), "r"(b[0]), "r"(b[1]));
}
static __device__ __forceinline__ float tanha(float x) {
    float y; asm("tanh.approx.f32 %0,%1;" : "=f"(y) : "f"(x)); return y;
}
static __device__ __forceinline__ float sigt(float x) { return fmaf(0.5f, tanha(0.5f * x), 0.5f); }

// B[n][k] (single fp16, no lo term): r 0-63, z 64-127, ni 128-191, nh 192-255.
// k: 0-63 Whh (ni zero), k64-71 Wih, k72 bias.
static __device__ void build_B(half* Bs,
                               const float* __restrict__ Wih, const float* __restrict__ Whh,
                               const float* __restrict__ bih, const float* __restrict__ bhh,
                               int tid) {
    for (int i = tid; i < 256 * KP; i += NTHR) {
        int n = i / KP, k = i % KP;
        float v = 0.0f;
        if (k < 64) {
            if (n < 128) v = Whh[n * 64 + k];
            else if (n >= 192) v = Whh[(n - 64) * 64 + k];
        } else if (k < 72) {
            if (n < 192) v = Wih[n * 8 + (k - 64)];
        } else if (k == 72) {
            v = (n < 128) ? bih[n] + bhh[n] : (n < 192 ? bih[n] : bhh[n - 64]);
        }
        Bs[i] = __float2half_rn(v);
    }
}

static __device__ __forceinline__ void load_frags(u32 fb, int warp, u32 (&Bh)[4][KC][2]) {
    #pragma unroll
    for (int q = 0; q < 4; q++) {
        u32 bq = fb + (u32)((warp + 8 * q) * 8 * RB);
        #pragma unroll
        for (int kc = 0; kc < KC; kc++) ldm2(Bh[q][kc], bq + kc * 32);
    }
}

// Two m-tile GEMM, 2-term (A_hi·B + A_lo·B). ni only at kc=4.
static __device__ __forceinline__ void gemm_step(u32 aHi0, u32 aHi1,
                                                 const u32 (&Bh)[4][KC][2], float (&D)[2][4][4]) {
    #pragma unroll
    for (int mt = 0; mt < 2; mt++)
        #pragma unroll
        for (int q = 0; q < 4; q++)
            #pragma unroll
            for (int e = 0; e < 4; e++) D[mt][q][e] = 0.0f;
    #pragma unroll
    for (int kc = 0; kc < KC; kc++) {
        u32 ah[2][4], al[2][4];
        ldm4(ah[0], aHi0 + kc * 32);
        ldm4(ah[1], aHi1 + kc * 32);
        ldm4(al[0], aHi0 + ALO + kc * 32);
        ldm4(al[1], aHi1 + ALO + kc * 32);
        #pragma unroll
        for (int mt = 0; mt < 2; mt++) {
            mmaop(D[mt][0], ah[mt], Bh[0][kc]); mmaop(D[mt][0], al[mt], Bh[0][kc]);
            mmaop(D[mt][1], ah[mt], Bh[1][kc]); mmaop(D[mt][1], al[mt], Bh[1][kc]);
            mmaop(D[mt][3], ah[mt], Bh[3][kc]); mmaop(D[mt][3], al[mt], Bh[3][kc]);
        }
        if (kc == KC - 1) {
            #pragma unroll
            for (int mt = 0; mt < 2; mt++) {
                mmaop(D[mt][2], ah[mt], Bh[2][kc]); mmaop(D[mt][2], al[mt], Bh[2][kc]);
            }
        }
    }
}

// Gates in regs; write h' (hi/lo) into next A buffer.
static __device__ __forceinline__ void epi(half* AhiN, half* AloN, int warp, int lane,
                                           float (&D)[2][4][4], float (&hold)[2][4]) {
    const int r0 = lane >> 2;
    const int c0 = warp * 8 + 2 * (lane & 3);
    #pragma unroll
    for (int mt = 0; mt < 2; mt++) {
        float h[4];
        #pragma unroll
        for (int j = 0; j < 4; j++) {
            float R = sigt(D[mt][0][j]);
            float Z = sigt(D[mt][1][j]);
            float N = tanha(fmaf(R, D[mt][3][j], D[mt][2][j]));
            h[j] = fmaf(Z, hold[mt][j] - N, N);
            hold[mt][j] = h[j];
        }
        int ra = mt * 16 + r0, rb = ra + 8;
        half2 h2a = __floats2half2_rn(h[0], h[1]);
        half2 l2a = __floats2half2_rn(h[0] - __low2float(h2a), h[1] - __high2float(h2a));
        half2 h2b = __floats2half2_rn(h[2], h[3]);
        half2 l2b = __floats2half2_rn(h[2] - __low2float(h2b), h[3] - __high2float(h2b));
        *(half2*)(AhiN + ra * KP + c0) = h2a;
        *(half2*)(AloN + ra * KP + c0) = l2a;
        *(half2*)(AhiN + rb * KP + c0) = h2b;
        *(half2*)(AloN + rb * KP + c0) = l2b;
    }
}

static __device__ __forceinline__ void stage_x(half* Ahi, half* Alo, int row, const float* v) {
    #pragma unroll
    for (int j = 0; j < 4; j++) {
        float a = v[2 * j], b = v[2 * j + 1];
        half2 h2 = __floats2half2_rn(a, b);
        half2 l2 = __floats2half2_rn(a - __low2float(h2), b - __high2float(h2));
        *(half2*)(Ahi + row * KP + 64 + 2 * j) = h2;
        *(half2*)(Alo + row * KP + 64 + 2 * j) = l2;
    }
}

// Out-projection: one scalar out for (row r, output oo).
static __device__ __forceinline__ float oproj(const half* Ahi, const half* Alo,
                                              const float* wo, float acc, int r, int oo) {
    const half2* rh = (const half2*)(Ahi + r * KP);
    const half2* rl = (const half2*)(Alo + r * KP);
    #pragma unroll 8
    for (int k2 = 0; k2 < 32; k2++) {
        float2 hq = __half22float2(rh[k2]);
        float2 lq = __half22float2(rl[k2]);
        acc = fmaf(hq.x + lq.x, wo[(2 * k2) * 8 + oo],
              fmaf(hq.y + lq.y, wo[(2 * k2 + 1) * 8 + oo], acc));
    }
    return acc;
}

__global__ __launch_bounds__(NTHR, 2)
void seq2seq_mma_kernel(const float* __restrict__ x,
                        const float* __restrict__ xy,
                        const float* __restrict__ eWih, const float* __restrict__ eWhh,
                        const float* __restrict__ ebih, const float* __restrict__ ebhh,
                        const float* __restrict__ dWih, const float* __restrict__ dWhh,
                        const float* __restrict__ dbih, const float* __restrict__ dbhh,
                        const float* __restrict__ Wout, const float* __restrict__ bout,
                        float* __restrict__ out)
{
    extern __shared__ char smem[];
    half*  Bs = (half*)(smem + SB);
    float* wo = (float*)(smem + SWOUT);
    float* bo = (float*)(smem + SBOUT);

    const int tid  = threadIdx.x;
    const int lane = tid & 31;
    const int warp = tid >> 5;
    const int rowb = blockIdx.x * ROWS;

    // ---- zero both A buffers, load wout/bout ----
    for (int i = tid * 16; i < SB; i += NTHR * 16) *(uint4*)(smem + i) = make_uint4(0, 0, 0, 0);
    for (int i = tid; i < 512; i += NTHR) { int k = i >> 3, o = i & 7; wo[i] = Wout[o * 64 + k]; }
    if (tid < 8) bo[tid] = bout[tid];
    __syncthreads();
    if (tid < ROWS) {
        ((half*)(smem + SA))[tid * KP + 72]        = __float2half(1.0f);
        ((half*)(smem + SA + ABUF))[tid * KP + 72] = __float2half(1.0f);
        const float4* p = (const float4*)(x + ((size_t)rowb + tid) * 8);
        float4 a = p[0], b = p[1];
        float v[8] = {a.x, a.y, a.z, a.w, b.x, b.y, b.z, b.w};
        stage_x((half*)(smem + SA), (half*)(smem + SA + ALO), tid, v);
    }
    __syncthreads();

    // ---- encoder B (single fp16 term) -> resident fragments ----
    u32 Bh[4][KC][2];
    const u32 fb = sptr(Bs) + (u32)((lane & 7) * RB + ((lane >> 3) & 1) * 16);

    build_B(Bs, eWih, eWhh, ebih, ebhh, tid);  __syncthreads();
    load_frags(fb, warp, Bh);                  __syncthreads();

    u32 aoff0, aoff1;
    {
        int t8 = lane >> 3, lr = lane & 7;
        aoff0 = (u32)((0 * 16 + (t8 & 1) * 8 + lr) * RB + (t8 >> 1) * 16);
        aoff1 = (u32)((1 * 16 + (t8 & 1) * 8 + lr) * RB + (t8 >> 1) * 16);
    }
    const u32 sbA = sptr(smem + SA);

    float D[2][4][4];
    float hold[2][4];
    #pragma unroll
    for (int mt = 0; mt < 2; mt++)
        #pragma unroll
        for (int j = 0; j < 4; j++) hold[mt][j] = 0.0f;

    int b = 0;

    // =========================== ENCODER (1 sync/step) ===========================
    for (int t = 0; t < SEQ; t++) {
        float xv[8];
        const bool pf = (tid < ROWS) && (t + 1 < SEQ);
        if (pf) {
            const float4* p = (const float4*)(x + ((size_t)(t + 1) * BATCH + rowb + tid) * 8);
            float4 a = p[0], c = p[1];
            xv[0]=a.x; xv[1]=a.y; xv[2]=a.z; xv[3]=a.w; xv[4]=c.x; xv[5]=c.y; xv[6]=c.z; xv[7]=c.w;
        }
        u32 ab = sbA + (u32)(b * ABUF);
        gemm_step(ab + aoff0, ab + aoff1, Bh, D);
        int nb = b ^ 1;
        half* AhiN = (half*)(smem + SA + nb * ABUF);
        half* AloN = AhiN + ALO / 2;
        epi(AhiN, AloN, warp, lane, D, hold);
        if (pf) stage_x(AhiN, AloN, tid, xv);
        __syncthreads();
        b = nb;
    }

    // ---- decoder B + xy[0] ----
    build_B(Bs, dWih, dWhh, dbih, dbhh, tid);  __syncthreads();
    load_frags(fb, warp, Bh);
    if (tid < ROWS) {
        const float4* p = (const float4*)(xy + ((size_t)rowb + tid) * 8);
        float4 a = p[0], c = p[1];
        float v[8] = {a.x, a.y, a.z, a.w, c.x, c.y, c.z, c.w};
        half* Ahi = (half*)(smem + SA + b * ABUF);
        stage_x(Ahi, Ahi + ALO / 2, tid, v);
    }
    __syncthreads();

    // =========================== DECODER ===========================
    const int orr = tid >> 3, oo = tid & 7;    // 32 rows x 8 outs = 256 threads
    const float bop = bo[oo];

    for (int t = 0; t < LAB; t++) {
        u32 ab = sbA + (u32)(b * ABUF);
        gemm_step(ab + aoff0, ab + aoff1, Bh, D);
        int nb = b ^ 1;
        half* AhiN = (half*)(smem + SA + nb * ABUF);
        half* AloN = AhiN + ALO / 2;
        epi(AhiN, AloN, warp, lane, D, hold);
        __syncthreads();                       // h_{t+1} visible

        {
            float acc = oproj(AhiN, AloN, wo, bop, orr, oo);
            out[((size_t)t * BATCH + rowb + orr) * 8 + oo] = acc;
            if (t + 1 < LAB) {                 // feedback x
                half hh = __float2half_rn(acc);
                AhiN[orr * KP + 64 + oo] = hh;
                AloN[orr * KP + 64 + oo] = __float2half_rn(acc - __half2float(hh));
            }
        }
        __syncthreads();
        b = nb;
    }
}

extern "C" void kernel_launch(void* const* d_in, const int* in_sizes, int n_in,
                              void* d_out, int out_size) {
    (void)in_sizes; (void)n_in; (void)out_size;
    cudaFuncSetAttribute(seq2seq_mma_kernel,
                         cudaFuncAttributeMaxDynamicSharedMemorySize, STOT);
    seq2seq_mma_kernel<<<NBLK, NTHR, STOT>>>(
        (const float*)d_in[0], (const float*)d_in[1],
        (const float*)d_in[2], (const float*)d_in[3],
        (const float*)d_in[4], (const float*)d_in[5],
        (const float*)d_in[6], (const float*)d_in[7],
        (const float*)d_in[8], (const float*)d_in[9],
        (const float*)d_in[10], (const float*)d_in[11],
        (float*)d_out);
}

// round 17
// speedup vs baseline: 1.4375x; 1.0094x over previous
#include <cuda_runtime.h>
#include <cuda_fp16.h>

typedef unsigned int u32;

#define SEQ   256
#define LAB   128
#define BATCH 8192
#define NTHR  128              // 4 warps x 16 rows = 64 rows/CTA
#define NBLK  (BATCH / 64)     // 128
#define KP    88
#define RB    176

// ---- SMEM ----
#define SB    0                // B [256][88] fp16
#define SWO   45056            // Wout frag area [8][88] fp16
#define STOT  46592

static __device__ __forceinline__ u32 sptr(const void* p) {
    return (u32)__cvta_generic_to_shared(p);
}
static __device__ __forceinline__ void ldm4(u32* r, u32 a) {
    asm volatile("ldmatrix.sync.aligned.m8n8.x4.shared.b16 {%0,%1,%2,%3},[%4];"
        : "=r"(r[0]), "=r"(r[1]), "=r"(r[2]), "=r"(r[3]) : "r"(a));
}
static __device__ __forceinline__ void ldm2(u32* r, u32 a) {
    asm volatile("ldmatrix.sync.aligned.m8n8.x2.shared.b16 {%0,%1},[%2];"
        : "=r"(r[0]), "=r"(r[1]) : "r"(a));
}
static __device__ __forceinline__ void mmaop(float* d, const u32* a, const u32* b) {
    asm volatile("mma.sync.aligned.m16n8k16.row.col.f32.f16.f16.f32 "
        "{%0,%1,%2,%3},{%4,%5,%6,%7},{%8,%9},{%0,%1,%2,%3};"
        : "+f"(d[0]), "+f"(d[1]), "+f"(d[2]), "+f"(d[3])
        : "r"(a[0]), "r"(a[1]), "r"(a[2]), "r"(a[3]), "r"(b[0]), "r"(b[1]));
}
static __device__ __forceinline__ float tanha(float x) {
    float y; asm("tanh.approx.f32 %0,%1;" : "=f"(y) : "f"(x)); return y;
}
static __device__ __forceinline__ float sigt(float x) { return fmaf(0.5f, tanha(0.5f * x), 0.5f); }
static __device__ __forceinline__ u32 packh2(float a, float b) {
    half2 h = __floats2half2_rn(a, b);
    return *(u32*)&h;
}
static __device__ __forceinline__ float2 unpkh2(u32 v) {
    return __half22float2(*(half2*)&v);
}

// B[n][k] single fp16: r 0-63, z 64-127, ni 128-191, nh 192-255.
// k: 0-63 Whh (ni zero), 64-71 Wih, 72 bias.
static __device__ void build_B(half* Bs,
                               const float* __restrict__ Wih, const float* __restrict__ Whh,
                               const float* __restrict__ bih, const float* __restrict__ bhh,
                               int tid) {
    for (int i = tid; i < 256 * KP; i += NTHR) {
        int n = i / KP, k = i % KP;
        float v = 0.0f;
        if (k < 64) {
            if (n < 128) v = Whh[n * 64 + k];
            else if (n >= 192) v = Whh[(n - 64) * 64 + k];
        } else if (k < 72) {
            if (n < 192) v = Wih[n * 8 + (k - 64)];
        } else if (k == 72) {
            v = (n < 128) ? bih[n] + bhh[n] : (n < 192 ? bih[n] : bhh[n - 64]);
        }
        Bs[i] = __float2half_rn(v);
    }
}

__global__ __launch_bounds__(NTHR, 1)
void seq2seq_mma_kernel(const float* __restrict__ x,
                        const float* __restrict__ xy,
                        const float* __restrict__ eWih, const float* __restrict__ eWhh,
                        const float* __restrict__ ebih, const float* __restrict__ ebhh,
                        const float* __restrict__ dWih, const float* __restrict__ dWhh,
                        const float* __restrict__ dbih, const float* __restrict__ dbhh,
                        const float* __restrict__ Wout, const float* __restrict__ bout,
                        float* __restrict__ out)
{
    extern __shared__ char smem[];
    half* Bs = (half*)(smem + SB);
    half* Wo = (half*)(smem + SWO);

    const int tid  = threadIdx.x;
    const int lane = tid & 31;
    const int warp = tid >> 5;
    const int r0   = lane >> 2;          // fragment row
    const int c2   = 2 * (lane & 3);     // fragment col pair
    const int rw   = blockIdx.x * 64 + warp * 16;
    const int gr0  = rw + r0, gr1 = rw + r0 + 8;

    // ---- build encoder B + Wout frag area ----
    build_B(Bs, eWih, eWhh, ebih, ebhh, tid);
    for (int i = tid; i < 8 * KP; i += NTHR) {
        int o = i / KP, k = i % KP;
        Wo[i] = (k < 64) ? __float2half_rn(Wout[o * 64 + k]) : __half(0);
    }
    __syncthreads();

    // ---- lane-fixed addresses ----
    const u32 bsB   = sptr(Bs);
    const u32 blane = (u32)(((lane >> 4) * 8 + (lane & 7)) * RB + ((lane >> 3) & 1) * 16);
    const u32 fbW   = sptr(Wo) + (u32)((lane & 7) * RB + ((lane >> 3) & 1) * 16);
    u32 bWo[4][2];
    #pragma unroll
    for (int kc = 0; kc < 4; kc++) ldm2(bWo[kc], fbW + kc * 32);
    const float boA = bout[c2], boB = bout[c2 + 1];
    const u32 abias = ((lane & 3) == 0) ? 0x00003C00u : 0u;   // k=72 -> 1.0

    // ---- state ----
    float hold[8][4];
    u32 AH[5][4], AL[5][4];
    #pragma unroll
    for (int nt = 0; nt < 8; nt++)
        #pragma unroll
        for (int j = 0; j < 4; j++) hold[nt][j] = 0.0f;
    #pragma unroll
    for (int kc = 0; kc < 5; kc++)
        #pragma unroll
        for (int j = 0; j < 4; j++) { AH[kc][j] = 0; AL[kc][j] = 0; }
    AH[4][2] = abias; AH[4][3] = abias;

    // stage x frag helper values
    float2 px0, px1;

    #define STAGE_X()                                                          \
    do {                                                                       \
        AH[4][0] = packh2(px0.x, px0.y);                                       \
        AH[4][1] = packh2(px1.x, px1.y);                                       \
        float2 hq0 = unpkh2(AH[4][0]), hq1 = unpkh2(AH[4][1]);                 \
        AL[4][0] = packh2(px0.x - hq0.x, px0.y - hq0.y);                       \
        AL[4][1] = packh2(px1.x - hq1.x, px1.y - hq1.y);                       \
    } while (0)

    px0 = *(const float2*)(x + (size_t)gr0 * 8 + c2);
    px1 = *(const float2*)(x + (size_t)gr1 * 8 + c2);
    STAGE_X();

    // One GRU step: wave1 (r,z) -> R,Z; wave2 (ni,nh) -> h'; updates AH/AL/hold.
    #define GRU_STEP()                                                         \
    do {                                                                       \
        float D1[2][8][4];                                                     \
        _Pragma("unroll")                                                      \
        for (int g = 0; g < 2; g++)                                            \
            _Pragma("unroll")                                                  \
            for (int nt = 0; nt < 8; nt++)                                     \
                _Pragma("unroll")                                              \
                for (int j = 0; j < 4; j++) D1[g][nt][j] = 0.0f;               \
        _Pragma("unroll")                                                      \
        for (int kc = 0; kc < 5; kc++)                                         \
            _Pragma("unroll")                                                  \
            for (int g = 0; g < 2; g++)                                        \
                _Pragma("unroll")                                              \
                for (int p = 0; p < 4; p++) {                                  \
                    u32 bf[4];                                                 \
                    ldm4(bf, bsB + blane + (u32)((g * 64 + p * 16) * RB) + kc * 32); \
                    mmaop(D1[g][2 * p],     AH[kc], bf);                       \
                    mmaop(D1[g][2 * p],     AL[kc], bf);                       \
                    mmaop(D1[g][2 * p + 1], AH[kc], bf + 2);                   \
                    mmaop(D1[g][2 * p + 1], AL[kc], bf + 2);                   \
                }                                                              \
        u32 Rp[8][2], Zp[8][2];                                                \
        _Pragma("unroll")                                                      \
        for (int nt = 0; nt < 8; nt++) {                                       \
            Rp[nt][0] = packh2(sigt(D1[0][nt][0]), sigt(D1[0][nt][1]));        \
            Rp[nt][1] = packh2(sigt(D1[0][nt][2]), sigt(D1[0][nt][3]));        \
            Zp[nt][0] = packh2(sigt(D1[1][nt][0]), sigt(D1[1][nt][1]));        \
            Zp[nt][1] = packh2(sigt(D1[1][nt][2]), sigt(D1[1][nt][3]));        \
        }                                                                      \
        float D2[2][8][4];                                                     \
        _Pragma("unroll")                                                      \
        for (int g = 0; g < 2; g++)                                            \
            _Pragma("unroll")                                                  \
            for (int nt = 0; nt < 8; nt++)                                     \
                _Pragma("unroll")                                              \
                for (int j = 0; j < 4; j++) D2[g][nt][j] = 0.0f;               \
        _Pragma("unroll")                                                      \
        for (int kc = 0; kc < 5; kc++) {                                       \
            _Pragma("unroll")                                                  \
            for (int p = 0; p < 4; p++) {                                      \
                u32 bf[4];                                                     \
                ldm4(bf, bsB + blane + (u32)((192 + p * 16) * RB) + kc * 32);  \
                mmaop(D2[1][2 * p],     AH[kc], bf);                           \
                mmaop(D2[1][2 * p],     AL[kc], bf);                           \
                mmaop(D2[1][2 * p + 1], AH[kc], bf + 2);                       \
                mmaop(D2[1][2 * p + 1], AL[kc], bf + 2);                       \
            }                                                                  \
            if (kc == 4) {                                                     \
                _Pragma("unroll")                                              \
                for (int p = 0; p < 4; p++) {                                  \
                    u32 bf[4];                                                 \
                    ldm4(bf, bsB + blane + (u32)((128 + p * 16) * RB) + kc * 32); \
                    mmaop(D2[0][2 * p],     AH[kc], bf);                       \
                    mmaop(D2[0][2 * p],     AL[kc], bf);                       \
                    mmaop(D2[0][2 * p + 1], AH[kc], bf + 2);                   \
                    mmaop(D2[0][2 * p + 1], AL[kc], bf + 2);                   \
                }                                                              \
            }                                                                  \
        }                                                                      \
        _Pragma("unroll")                                                      \
        for (int nt = 0; nt < 8; nt++) {                                       \
            float2 Rq0 = unpkh2(Rp[nt][0]), Rq1 = unpkh2(Rp[nt][1]);           \
            float2 Zq0 = unpkh2(Zp[nt][0]), Zq1 = unpkh2(Zp[nt][1]);           \
            float Rv[4] = {Rq0.x, Rq0.y, Rq1.x, Rq1.y};                        \
            float Zv[4] = {Zq0.x, Zq0.y, Zq1.x, Zq1.y};                        \
            _Pragma("unroll")                                                  \
            for (int j = 0; j < 4; j++) {                                      \
                float N = tanha(fmaf(Rv[j], D2[1][nt][j], D2[0][nt][j]));      \
                hold[nt][j] = fmaf(Zv[j], hold[nt][j] - N, N);                 \
            }                                                                  \
        }                                                                      \
        _Pragma("unroll")                                                      \
        for (int kc = 0; kc < 4; kc++) {                                       \
            int e = 2 * kc, o = 2 * kc + 1;                                    \
            AH[kc][0] = packh2(hold[e][0], hold[e][1]);                        \
            AH[kc][1] = packh2(hold[e][2], hold[e][3]);                        \
            AH[kc][2] = packh2(hold[o][0], hold[o][1]);                        \
            AH[kc][3] = packh2(hold[o][2], hold[o][3]);                        \
            float2 q0 = unpkh2(AH[kc][0]), q1 = unpkh2(AH[kc][1]);             \
            float2 q2 = unpkh2(AH[kc][2]), q3 = unpkh2(AH[kc][3]);             \
            AL[kc][0] = packh2(hold[e][0] - q0.x, hold[e][1] - q0.y);          \
            AL[kc][1] = packh2(hold[e][2] - q1.x, hold[e][3] - q1.y);          \
            AL[kc][2] = packh2(hold[o][0] - q2.x, hold[o][1] - q2.y);          \
            AL[kc][3] = packh2(hold[o][2] - q3.x, hold[o][3] - q3.y);          \
        }                                                                      \
    } while (0)

    // =========================== ENCODER (no barriers) ===========================
    for (int t = 0; t < SEQ; t++) {
        float2 nx0, nx1;
        if (t + 1 < SEQ) {
            nx0 = *(const float2*)(x + ((size_t)(t + 1) * BATCH + gr0) * 8 + c2);
            nx1 = *(const float2*)(x + ((size_t)(t + 1) * BATCH + gr1) * 8 + c2);
        }
        GRU_STEP();
        if (t + 1 < SEQ) { px0 = nx0; px1 = nx1; STAGE_X(); }
    }

    // ---- phase swap ----
    __syncthreads();
    build_B(Bs, dWih, dWhh, dbih, dbhh, tid);
    __syncthreads();

    px0 = *(const float2*)(xy + (size_t)gr0 * 8 + c2);
    px1 = *(const float2*)(xy + (size_t)gr1 * 8 + c2);
    STAGE_X();

    // =========================== DECODER (no barriers) ===========================
    for (int t = 0; t < LAB; t++) {
        GRU_STEP();                              // h_{t+1} in AH/AL

        // out(t) = h_{t+1} @ Wout^T + bout  (D frag == x-feedback frag)
        float Dو[4] = {0.0f, 0.0f, 0.0f, 0.0f};
        #pragma unroll
        for (int kc = 0; kc < 4; kc++) {
            mmaop(Dو, AH[kc], bWo[kc]);
            mmaop(Dو, AL[kc], bWo[kc]);
        }
        float o0 = Dو[0] + boA, o1 = Dو[1] + boB;
        float o2 = Dو[2] + boA, o3 = Dو[3] + boB;

        *(float2*)(out + ((size_t)t * BATCH + gr0) * 8 + c2) = make_float2(o0, o1);
        *(float2*)(out + ((size_t)t * BATCH + gr1) * 8 + c2) = make_float2(o2, o3);

        if (t + 1 < LAB) {                       // feedback x frag
            px0 = make_float2(o0, o1);
            px1 = make_float2(o2, o3);
            STAGE_X();
        }
    }
}

extern "C" void kernel_launch(void* const* d_in, const int* in_sizes, int n_in,
                              void* d_out, int out_size) {
    (void)in_sizes; (void)n_in; (void)out_size;
    cudaFuncSetAttribute(seq2seq_mma_kernel,
                         cudaFuncAttributeMaxDynamicSharedMemorySize, STOT);
    seq2seq_mma_kernel<<<NBLK, NTHR, STOT>>>(
        (const float*)d_in[0], (const float*)d_in[1],
        (const float*)d_in[2], (const float*)d_in[3],
        (const float*)d_in[4], (const float*)d_in[5],
        (const float*)d_in[6], (const float*)d_in[7],
        (const float*)d_in[8], (const float*)d_in[9],
        (const float*)d_in[10], (const float*)d_in[11],
        (float*)d_out);
}